// round 5
// baseline (speedup 1.0000x reference)
#include <cuda_runtime.h>
#include <cuda_bf16.h>
#include <math.h>

// ---------------- problem constants ----------------
#define kB    16
#define kLIN  400
#define kT    100
#define kD    512
#define kH    8
#define kDep  64
#define kDFF  2048
#define kV    32000
#define kOOV  100
#define kVE   (kV + kOOV)   // 32100

// ---------------- scratch (device globals; no runtime alloc) ----------------
__device__ float g_pe [kLIN * kD];
__device__ float g_xe [kB * kLIN * kD];
__device__ float g_q  [kB * kLIN * kD];
__device__ float g_k  [kB * kLIN * kD];
__device__ float g_v  [kB * kLIN * kD];
__device__ float g_t  [kB * kLIN * kD];
__device__ float g_sc [kB * kH * kLIN * kLIN];   // enc scores / dec self scores
__device__ float g_cs [kB * kH * kT * kLIN];     // cross scores (block2)
__device__ float g_ffn[kB * kLIN * kDFF];
__device__ float g_xd [kB * kT * kD];            // decoder embedding (+pe), fixed
__device__ float g_emb[kB * kT * kD];            // raw decoder embedding
__device__ float g_o1 [kB * kT * kD];
__device__ float g_o2 [kB * kT * kD];
__device__ float g_do [kB * kT * kD];            // dec_out
__device__ float g_pg [kB * kT];
__device__ float g_am [kB * kT * kLIN];

// ---------------- helpers ----------------
__device__ __forceinline__ float warp_sum(float v) {
    #pragma unroll
    for (int o = 16; o > 0; o >>= 1) v += __shfl_xor_sync(0xffffffffu, v, o);
    return v;
}
__device__ __forceinline__ float warp_max(float v) {
    #pragma unroll
    for (int o = 16; o > 0; o >>= 1) v = fmaxf(v, __shfl_xor_sync(0xffffffffu, v, o));
    return v;
}

// ---------------- positional encoding ----------------
__global__ void pe_kernel(float* __restrict__ pe) {
    int i = blockIdx.x * 256 + threadIdx.x;
    if (i >= kLIN * kD) return;
    int pos = i / kD, d = i % kD;
    double rate = exp(-(double)(2 * (d / 2)) / (double)kD * log(10000.0));
    double ang  = (double)pos * rate;
    pe[i] = (float)((d & 1) ? cos(ang) : sin(ang));
}

// ---------------- embeddings ----------------
__global__ void embed_enc_kernel(const int* __restrict__ idx, const float* __restrict__ emb,
                                 const float* __restrict__ pe, float* __restrict__ x) {
    int t = blockIdx.x * 256 + threadIdx.x;
    if (t >= kB * kLIN * kD) return;
    int d = t & (kD - 1);
    int bs = t >> 9;             // b*LIN + s
    int s  = bs % kLIN;
    float scale = sqrtf((float)kD);
    x[t] = emb[(size_t)idx[bs] * kD + d] * scale + pe[s * kD + d];
}
__global__ void embed_dec_kernel(const int* __restrict__ idx, const float* __restrict__ emb,
                                 const float* __restrict__ pe, float* __restrict__ x,
                                 float* __restrict__ eraw) {
    int t = blockIdx.x * 256 + threadIdx.x;
    if (t >= kB * kT * kD) return;
    int d = t & (kD - 1);
    int bs = t >> 9;
    int s  = bs % kT;
    float e = emb[(size_t)idx[bs] * kD + d];
    eraw[t] = e;
    float scale = sqrtf((float)kD);
    x[t] = e * scale + pe[s * kD + d];
}

// ---------------- generic GEMM: C[M,N] = A[M,K] @ W[K,N] + bias, epilogue ----------------
// tile 64x64, BK=16, 256 threads, 4x4 microtile. M%64==0, N%64==0, K%16==0 (holds for all calls).
__global__ void __launch_bounds__(256)
gemm_kernel(const float* __restrict__ A, const float* __restrict__ W,
            const float* __restrict__ bias, float* __restrict__ C,
            int M, int N, int K, int ldc, int relu, const float* __restrict__ rs) {
    __shared__ float As[16][68];
    __shared__ float Bs[16][68];
    int tid = threadIdx.x;
    int bm = blockIdx.y << 6, bn = blockIdx.x << 6;
    int tx = tid & 15, ty = tid >> 4;
    int arow = tid >> 2, acol = (tid & 3) << 2;
    int wrow = tid >> 4, wcol = (tid & 15) << 2;
    const float* Ap = A + (size_t)(bm + arow) * K + acol;
    const float* Wp = W + (size_t)wrow * N + bn + wcol;
    float acc[4][4] = {};
    for (int k0 = 0; k0 < K; k0 += 16) {
        float4 av = *(const float4*)(Ap + k0);
        float4 wv = *(const float4*)(Wp + (size_t)k0 * N);
        As[acol + 0][arow] = av.x; As[acol + 1][arow] = av.y;
        As[acol + 2][arow] = av.z; As[acol + 3][arow] = av.w;
        *(float4*)&Bs[wrow][wcol] = wv;
        __syncthreads();
        #pragma unroll
        for (int kk = 0; kk < 16; ++kk) {
            float4 a4 = *(const float4*)&As[kk][ty << 2];
            float4 b4 = *(const float4*)&Bs[kk][tx << 2];
            float a[4] = {a4.x, a4.y, a4.z, a4.w};
            float b[4] = {b4.x, b4.y, b4.z, b4.w};
            #pragma unroll
            for (int i = 0; i < 4; ++i)
                #pragma unroll
                for (int j = 0; j < 4; ++j)
                    acc[i][j] = fmaf(a[i], b[j], acc[i][j]);
        }
        __syncthreads();
    }
    #pragma unroll
    for (int i = 0; i < 4; ++i) {
        int row = bm + (ty << 2) + i;
        float scale = rs ? rs[row] : 1.0f;
        #pragma unroll
        for (int j = 0; j < 4; ++j) {
            int col = bn + (tx << 2) + j;
            float vv = acc[i][j] + bias[col];
            if (relu) vv = fmaxf(vv, 0.0f);
            C[(size_t)row * ldc + col] = vv * scale;
        }
    }
}

// ---------------- attention scores: S[b,h,q,k] = q.k/8 + mask*(-1e9) ----------------
// mode 0: mask[b*Sk + k]   (padding masks)
// mode 1: mask[b*Sq*Sk + q*Sk + k] (look-ahead, Sq==Sk==T)
__global__ void __launch_bounds__(256)
scores_kernel(const float* __restrict__ Q, const float* __restrict__ Kt,
              float* __restrict__ S, int Sq, int Sk,
              const float* __restrict__ mask, int mode) {
    __shared__ float Qs[32][68];
    __shared__ float Ks[32][68];
    int tid = threadIdx.x;
    int bh = blockIdx.z, b = bh >> 3, h = bh & 7;
    int q0 = blockIdx.y * 32, k0 = blockIdx.x * 32;
    for (int i = tid; i < 32 * 16; i += 256) {
        int r = i >> 4, c4 = (i & 15) << 2;
        float4 qv = make_float4(0, 0, 0, 0), kv = make_float4(0, 0, 0, 0);
        int qr = q0 + r, kr = k0 + r;
        if (qr < Sq) qv = *(const float4*)&Q[((size_t)(b * Sq + qr)) * kD + h * kDep + c4];
        if (kr < Sk) kv = *(const float4*)&Kt[((size_t)(b * Sk + kr)) * kD + h * kDep + c4];
        *(float4*)&Qs[r][c4] = qv;
        *(float4*)&Ks[r][c4] = kv;
    }
    __syncthreads();
    int tx = tid & 15, ty = tid >> 4;
    float acc[2][2] = {};
    #pragma unroll
    for (int d4 = 0; d4 < kDep; d4 += 4) {
        float4 a0 = *(const float4*)&Qs[ty * 2 + 0][d4];
        float4 a1 = *(const float4*)&Qs[ty * 2 + 1][d4];
        float4 b0 = *(const float4*)&Ks[tx * 2 + 0][d4];
        float4 b1 = *(const float4*)&Ks[tx * 2 + 1][d4];
        acc[0][0] += a0.x*b0.x + a0.y*b0.y + a0.z*b0.z + a0.w*b0.w;
        acc[0][1] += a0.x*b1.x + a0.y*b1.y + a0.z*b1.z + a0.w*b1.w;
        acc[1][0] += a1.x*b0.x + a1.y*b0.y + a1.z*b0.z + a1.w*b0.w;
        acc[1][1] += a1.x*b1.x + a1.y*b1.y + a1.z*b1.z + a1.w*b1.w;
    }
    #pragma unroll
    for (int i = 0; i < 2; ++i) {
        int qg = q0 + ty * 2 + i;
        #pragma unroll
        for (int j = 0; j < 2; ++j) {
            int kg = k0 + tx * 2 + j;
            if (qg < Sq && kg < Sk) {
                float vv = acc[i][j] * 0.125f;   // 1/sqrt(64)
                float mk = (mode == 0) ? mask[(size_t)b * Sk + kg]
                                       : mask[((size_t)b * Sq + qg) * Sk + kg];
                vv += mk * (-1e9f);
                S[((size_t)bh * Sq + qg) * Sk + kg] = vv;
            }
        }
    }
}

// ---------------- row softmax (in place) ----------------
__global__ void softmax_kernel(float* __restrict__ S, int len) {
    float* p = S + (size_t)blockIdx.x * len;
    int tid = threadIdx.x;
    __shared__ float sh[4];
    float m = -1e30f;
    for (int i = tid; i < len; i += 128) m = fmaxf(m, p[i]);
    m = warp_max(m);
    if ((tid & 31) == 0) sh[tid >> 5] = m;
    __syncthreads();
    m = fmaxf(fmaxf(sh[0], sh[1]), fmaxf(sh[2], sh[3]));
    float s = 0.0f;
    for (int i = tid; i < len; i += 128) { float e = __expf(p[i] - m); p[i] = e; s += e; }
    s = warp_sum(s);
    __syncthreads();
    if ((tid & 31) == 0) sh[tid >> 5] = s;
    __syncthreads();
    float inv = 1.0f / (sh[0] + sh[1] + sh[2] + sh[3]);
    for (int i = tid; i < len; i += 128) p[i] *= inv;
}

// ---------------- O[b,q,h*64+d] = sum_k P[b,h,q,k] * V[b,k,h*64+d] ----------------
__global__ void __launch_bounds__(256)
attn_out_kernel(const float* __restrict__ P, const float* __restrict__ V,
                float* __restrict__ O, int Sq, int Sk) {
    __shared__ float Ps[32][33];
    __shared__ float Vs[32][64];
    int tid = threadIdx.x;
    int bh = blockIdx.y, b = bh >> 3, h = bh & 7;
    int q0 = blockIdx.x * 32;
    const float* p = P + (size_t)bh * Sq * Sk;
    int dcol = tid & 63, qb = tid >> 6;
    float acc[8] = {};
    for (int k0 = 0; k0 < Sk; k0 += 32) {
        {
            int r = tid >> 3, c = (tid & 7) << 2;
            int qg = q0 + r, kg = k0 + c;
            float4 v4 = make_float4(0, 0, 0, 0);
            if (qg < Sq && kg < Sk)       // Sk % 4 == 0 always
                v4 = *(const float4*)&p[(size_t)qg * Sk + kg];
            Ps[r][c] = v4.x; Ps[r][c + 1] = v4.y; Ps[r][c + 2] = v4.z; Ps[r][c + 3] = v4.w;
        }
        for (int i = tid; i < 32 * 16; i += 256) {
            int r = i >> 4, c4 = (i & 15) << 2;
            int kg = k0 + r;
            float4 v4 = make_float4(0, 0, 0, 0);
            if (kg < Sk) v4 = *(const float4*)&V[((size_t)(b * Sk + kg)) * kD + h * kDep + c4];
            *(float4*)&Vs[r][c4] = v4;
        }
        __syncthreads();
        #pragma unroll
        for (int kk = 0; kk < 32; ++kk) {
            float vv = Vs[kk][dcol];
            #pragma unroll
            for (int j = 0; j < 8; ++j)
                acc[j] = fmaf(Ps[qb + (j << 2)][kk], vv, acc[j]);
        }
        __syncthreads();
    }
    #pragma unroll
    for (int j = 0; j < 8; ++j) {
        int qg = q0 + qb + (j << 2);
        if (qg < Sq) O[((size_t)(b * Sq + qg)) * kD + h * kDep + dcol] = acc[j];
    }
}

// ---------------- y = LN(x + a) * g + b ----------------
__global__ void add_ln_kernel(const float* __restrict__ x, const float* __restrict__ a,
                              float* __restrict__ y, const float* __restrict__ g,
                              const float* __restrict__ bb) {
    int row = blockIdx.x, tid = threadIdx.x;
    size_t base = (size_t)row * kD;
    float v[4], s = 0.0f, s2 = 0.0f;
    #pragma unroll
    for (int j = 0; j < 4; ++j) {
        int d = tid + j * 128;
        float t = x[base + d] + a[base + d];
        v[j] = t; s += t; s2 += t * t;
    }
    __shared__ float shs[4], shs2[4];
    s = warp_sum(s); s2 = warp_sum(s2);
    if ((tid & 31) == 0) { shs[tid >> 5] = s; shs2[tid >> 5] = s2; }
    __syncthreads();
    float S = shs[0] + shs[1] + shs[2] + shs[3];
    float S2 = shs2[0] + shs2[1] + shs2[2] + shs2[3];
    float mu = S * (1.0f / kD);
    float var = S2 * (1.0f / kD) - mu * mu;
    float rstd = rsqrtf(var + 1e-6f);
    #pragma unroll
    for (int j = 0; j < 4; ++j) {
        int d = tid + j * 128;
        y[base + d] = (v[j] - mu) * rstd * g[d] + bb[d];
    }
}

// ---------------- p_gen ----------------
__global__ void pgen_kernel(const float* __restrict__ ctx, const float* __restrict__ dec,
                            const float* __restrict__ emb, const float* __restrict__ w,
                            const float* __restrict__ bvec, float* __restrict__ pg) {
    int row = blockIdx.x, tid = threadIdx.x;
    float s = 0.0f;
    for (int d = tid; d < kD; d += 128) {
        size_t o = (size_t)row * kD + d;
        s += ctx[o] * w[d] + dec[o] * w[kD + d] + emb[o] * w[2 * kD + d];
    }
    __shared__ float sh[4];
    s = warp_sum(s);
    if ((tid & 31) == 0) sh[tid >> 5] = s;
    __syncthreads();
    if (tid == 0) {
        float t = sh[0] + sh[1] + sh[2] + sh[3] + bvec[0] + bvec[1] + bvec[2];
        pg[row] = 1.0f / (1.0f + expf(-t));
    }
}

// ---------------- attn_mean[b,t,l] = sum_h block2 / H ----------------
__global__ void attn_mean_kernel(const float* __restrict__ P, float* __restrict__ am) {
    int i = blockIdx.x * 256 + threadIdx.x;
    if (i >= kB * kT * kLIN) return;
    int l = i % kLIN;
    int bt = i / kLIN;
    int b = bt / kT, t = bt % kT;
    float s = 0.0f;
    #pragma unroll
    for (int h = 0; h < kH; ++h)
        s += P[(((size_t)(b * kH + h) * kT) + t) * kLIN + l];
    am[i] = s * (1.0f / kH);
}

// ---------------- zero extension columns [V, V+100) ----------------
__global__ void zero_ext_kernel(float* __restrict__ out) {
    int i = blockIdx.x * 256 + threadIdx.x;
    if (i >= kB * kT * kOOV) return;
    int row = i / kOOV, c = i % kOOV;
    out[(size_t)row * kVE + kV + c] = 0.0f;
}

// ---------------- copy scatter: out[b,t,ext[b,l]] += (1-pg)*am ----------------
__global__ void scatter_kernel(float* __restrict__ out, const float* __restrict__ am,
                               const float* __restrict__ pg, const int* __restrict__ ext) {
    int i = blockIdx.x * 256 + threadIdx.x;
    if (i >= kB * kT * kLIN) return;
    int l = i % kLIN;
    int bt = i / kLIN;
    int b = bt / kT;
    float v = (1.0f - pg[bt]) * am[i];
    int vi = ext[b * kLIN + l];
    atomicAdd(&out[(size_t)bt * kVE + vi], v);
}

// ---------------- host orchestration ----------------
extern "C" void kernel_launch(void* const* d_in, const int* in_sizes, int n_in,
                              void* d_out, int out_size) {
    // input layout: [inp, tar, extended_inp, enc_mask, la_mask, dec_mask, (max_oov?), weights...]
    int off = (n_in > 6 && in_sizes[6] == 1) ? 1 : 0;
    const int*   inp      = (const int*)d_in[0];
    const int*   tar      = (const int*)d_in[1];
    const int*   ext      = (const int*)d_in[2];
    const float* enc_mask = (const float*)d_in[3];
    const float* la_mask  = (const float*)d_in[4];
    const float* dec_mask = (const float*)d_in[5];
    const float* emb_enc  = (const float*)d_in[6 + off];
    const float* emb_dec  = (const float*)d_in[7 + off];
    const float* eaw = (const float*)d_in[8 + off];
    const float* eab = (const float*)d_in[9 + off];
    const float* ew1 = (const float*)d_in[10 + off];
    const float* eb1 = (const float*)d_in[11 + off];
    const float* ew2 = (const float*)d_in[12 + off];
    const float* eb2 = (const float*)d_in[13 + off];
    const float* elg = (const float*)d_in[14 + off];
    const float* elb = (const float*)d_in[15 + off];
    const float* daw = (const float*)d_in[16 + off];
    const float* dab = (const float*)d_in[17 + off];
    const float* dw1 = (const float*)d_in[18 + off];
    const float* db1 = (const float*)d_in[19 + off];
    const float* dw2 = (const float*)d_in[20 + off];
    const float* db2 = (const float*)d_in[21 + off];
    const float* dlg = (const float*)d_in[22 + off];
    const float* dlb = (const float*)d_in[23 + off];
    const float* ptrw = (const float*)d_in[24 + off];
    const float* ptrb = (const float*)d_in[25 + off];
    const float* fw  = (const float*)d_in[26 + off];
    const float* fb  = (const float*)d_in[27 + off];
    float* out = (float*)d_out;

    float *pe_, *xe_, *q_, *k_, *v_, *t_, *sc_, *cs_, *ffn_, *xd_, *emb_, *o1_, *o2_, *do_, *pg_, *am_;
    cudaGetSymbolAddress((void**)&pe_,  g_pe);
    cudaGetSymbolAddress((void**)&xe_,  g_xe);
    cudaGetSymbolAddress((void**)&q_,   g_q);
    cudaGetSymbolAddress((void**)&k_,   g_k);
    cudaGetSymbolAddress((void**)&v_,   g_v);
    cudaGetSymbolAddress((void**)&t_,   g_t);
    cudaGetSymbolAddress((void**)&sc_,  g_sc);
    cudaGetSymbolAddress((void**)&cs_,  g_cs);
    cudaGetSymbolAddress((void**)&ffn_, g_ffn);
    cudaGetSymbolAddress((void**)&xd_,  g_xd);
    cudaGetSymbolAddress((void**)&emb_, g_emb);
    cudaGetSymbolAddress((void**)&o1_,  g_o1);
    cudaGetSymbolAddress((void**)&o2_,  g_o2);
    cudaGetSymbolAddress((void**)&do_,  g_do);
    cudaGetSymbolAddress((void**)&pg_,  g_pg);
    cudaGetSymbolAddress((void**)&am_,  g_am);

    auto gemm = [&](const float* A, const float* W, const float* bias, float* C,
                    int M, int N, int K, int ldc, int relu, const float* rs) {
        dim3 grid(N / 64, M / 64);
        gemm_kernel<<<grid, 256>>>(A, W, bias, C, M, N, K, ldc, relu, rs);
    };

    const int ME = kB * kLIN;  // 6400
    const int MD = kB * kT;    // 1600
    const size_t DD2 = (size_t)kD * kD;

    pe_kernel<<<(kLIN * kD + 255) / 256, 256>>>(pe_);
    embed_enc_kernel<<<(kB * kLIN * kD + 255) / 256, 256>>>(inp, emb_enc, pe_, xe_);

    // ================= encoder (x chains through both layers) =================
    for (int i = 0; i < 2; ++i) {
        const float* w = eaw + (size_t)i * 4 * DD2;
        const float* b = eab + (size_t)i * 4 * kD;
        gemm(xe_, w + 0 * DD2, b + 0 * kD, q_, ME, kD, kD, kD, 0, nullptr);
        gemm(xe_, w + 1 * DD2, b + 1 * kD, k_, ME, kD, kD, kD, 0, nullptr);
        gemm(xe_, w + 2 * DD2, b + 2 * kD, v_, ME, kD, kD, kD, 0, nullptr);
        dim3 sg((kLIN + 31) / 32, (kLIN + 31) / 32, kB * kH);
        scores_kernel<<<sg, 256>>>(q_, k_, sc_, kLIN, kLIN, enc_mask, 0);
        softmax_kernel<<<kB * kH * kLIN, 128>>>(sc_, kLIN);
        dim3 og((kLIN + 31) / 32, kB * kH);
        attn_out_kernel<<<og, 256>>>(sc_, v_, t_, kLIN, kLIN);
        gemm(t_, w + 3 * DD2, b + 3 * kD, q_, ME, kD, kD, kD, 0, nullptr);
        add_ln_kernel<<<ME, 128>>>(xe_, q_, xe_, elg + (i * 2 + 0) * kD, elb + (i * 2 + 0) * kD);
        gemm(xe_, ew1 + (size_t)i * kD * kDFF, eb1 + (size_t)i * kDFF, ffn_, ME, kDFF, kD, kDFF, 1, nullptr);
        gemm(ffn_, ew2 + (size_t)i * kDFF * kD, eb2 + (size_t)i * kD, q_, ME, kD, kDFF, kD, 0, nullptr);
        add_ln_kernel<<<ME, 128>>>(xe_, q_, xe_, elg + (i * 2 + 1) * kD, elb + (i * 2 + 1) * kD);
    }

    // ================= decoder =================
    // NOTE: in the reference, xd is NEVER updated inside the decoder loop — every
    // layer's self-attention reads the original embedding, and dec_out/block2 from
    // all but the LAST layer are dead. So we compute only layer i = L-1 = 1.
    embed_dec_kernel<<<(kB * kT * kD + 255) / 256, 256>>>(tar, emb_dec, pe_, xd_, emb_);
    {
        const int i = 1;   // last (and only live) decoder layer
        const float* w0 = daw + (size_t)(i * 2 + 0) * 4 * DD2;
        const float* b0 = dab + (size_t)(i * 2 + 0) * 4 * kD;
        const float* w1 = daw + (size_t)(i * 2 + 1) * 4 * DD2;
        const float* b1 = dab + (size_t)(i * 2 + 1) * 4 * kD;
        // self attention (causal) on xd (embedding + pe)
        gemm(xd_, w0 + 0 * DD2, b0 + 0 * kD, q_, MD, kD, kD, kD, 0, nullptr);
        gemm(xd_, w0 + 1 * DD2, b0 + 1 * kD, k_, MD, kD, kD, kD, 0, nullptr);
        gemm(xd_, w0 + 2 * DD2, b0 + 2 * kD, v_, MD, kD, kD, kD, 0, nullptr);
        scores_kernel<<<dim3((kT + 31) / 32, (kT + 31) / 32, kB * kH), 256>>>(q_, k_, sc_, kT, kT, la_mask, 1);
        softmax_kernel<<<kB * kH * kT, 128>>>(sc_, kT);
        attn_out_kernel<<<dim3((kT + 31) / 32, kB * kH), 256>>>(sc_, v_, t_, kT, kT);
        gemm(t_, w0 + 3 * DD2, b0 + 3 * kD, q_, MD, kD, kD, kD, 0, nullptr);
        add_ln_kernel<<<MD, 128>>>(xd_, q_, o1_, dlg + (i * 3 + 0) * kD, dlb + (i * 3 + 0) * kD);
        // cross attention against encoder output
        gemm(o1_, w1 + 0 * DD2, b1 + 0 * kD, q_, MD, kD, kD, kD, 0, nullptr);
        gemm(xe_, w1 + 1 * DD2, b1 + 1 * kD, k_, ME, kD, kD, kD, 0, nullptr);
        gemm(xe_, w1 + 2 * DD2, b1 + 2 * kD, v_, ME, kD, kD, kD, 0, nullptr);
        scores_kernel<<<dim3((kLIN + 31) / 32, (kT + 31) / 32, kB * kH), 256>>>(q_, k_, cs_, kT, kLIN, dec_mask, 0);
        softmax_kernel<<<kB * kH * kT, 128>>>(cs_, kLIN);
        attn_out_kernel<<<dim3((kT + 31) / 32, kB * kH), 256>>>(cs_, v_, t_, kT, kLIN);
        gemm(t_, w1 + 3 * DD2, b1 + 3 * kD, q_, MD, kD, kD, kD, 0, nullptr);
        add_ln_kernel<<<MD, 128>>>(o1_, q_, o2_, dlg + (i * 3 + 1) * kD, dlb + (i * 3 + 1) * kD);
        // ffn
        gemm(o2_, dw1 + (size_t)i * kD * kDFF, db1 + (size_t)i * kDFF, ffn_, MD, kDFF, kD, kDFF, 1, nullptr);
        gemm(ffn_, dw2 + (size_t)i * kDFF * kD, db2 + (size_t)i * kD, q_, MD, kD, kDFF, kD, 0, nullptr);
        add_ln_kernel<<<MD, 128>>>(o2_, q_, do_, dlg + (i * 3 + 2) * kD, dlb + (i * 3 + 2) * kD);
    }

    // ================= pointer-generator head =================
    // context = block2 @ enc_heads  (same layout as attention output)
    attn_out_kernel<<<dim3((kT + 31) / 32, kB * kH), 256>>>(cs_, xe_, t_, kT, kLIN);
    pgen_kernel<<<MD, 128>>>(t_, do_, emb_, ptrw, ptrb, pg_);
    // final logits scaled by p_gen, written directly into extended output rows (ldc = V+100)
    gemm(do_, fw, fb, out, MD, kV, kD, kVE, 0, pg_);
    zero_ext_kernel<<<(kB * kT * kOOV + 255) / 256, 256>>>(out);
    attn_mean_kernel<<<(kB * kT * kLIN + 255) / 256, 256>>>(cs_, am_);
    if (out_size >= kB * kT * kVE + kB * kT * kLIN)
        cudaMemcpyAsync(out + (size_t)kB * kT * kVE, am_,
                        sizeof(float) * kB * kT * kLIN, cudaMemcpyDeviceToDevice, 0);
    scatter_kernel<<<(kB * kT * kLIN + 255) / 256, 256>>>(out, am_, pg_, ext);
}

// round 6
// speedup vs baseline: 1.1634x; 1.1634x over previous
#include <cuda_runtime.h>
#include <cuda_bf16.h>
#include <math.h>
#include <stdint.h>

// ---------------- problem constants ----------------
#define kB    16
#define kLIN  400
#define kT    100
#define kD    512
#define kH    8
#define kDep  64
#define kDFF  2048
#define kV    32000
#define kOOV  100
#define kVE   (kV + kOOV)   // 32100

// ---------------- scratch (device globals; no runtime alloc) ----------------
__device__ float g_pe [kLIN * kD];
__device__ float g_xe [kB * kLIN * kD];
__device__ float g_q  [kB * kLIN * kD];
__device__ float g_k  [kB * kLIN * kD];
__device__ float g_v  [kB * kLIN * kD];
__device__ float g_t  [kB * kLIN * kD];
__device__ float g_sc [kB * kH * kLIN * kLIN];   // enc scores / dec self scores
__device__ float g_cs [kB * kH * kT * kLIN];     // cross scores (block2)
__device__ float g_ffn[kB * kLIN * kDFF];
__device__ float g_xd [kB * kT * kD];            // decoder embedding (+pe)
__device__ float g_emb[kB * kT * kD];            // raw decoder embedding
__device__ float g_o1 [kB * kT * kD];
__device__ float g_o2 [kB * kT * kD];
__device__ float g_do [kB * kT * kD];            // dec_out
__device__ float g_pg [kB * kT];
__device__ float g_am [kB * kT * kLIN];

// ---------------- helpers ----------------
__device__ __forceinline__ float warp_sum(float v) {
    #pragma unroll
    for (int o = 16; o > 0; o >>= 1) v += __shfl_xor_sync(0xffffffffu, v, o);
    return v;
}
__device__ __forceinline__ float warp_max(float v) {
    #pragma unroll
    for (int o = 16; o > 0; o >>= 1) v = fmaxf(v, __shfl_xor_sync(0xffffffffu, v, o));
    return v;
}
__device__ __forceinline__ uint32_t f2tf32(float x) {
    uint32_t r;
    asm("cvt.rna.tf32.f32 %0, %1;" : "=r"(r) : "f"(x));
    return r;
}
__device__ __forceinline__ void mma_tf32(float (&d)[4], const uint32_t (&a)[4], const uint32_t (&b)[2]) {
    asm volatile(
        "mma.sync.aligned.m16n8k8.row.col.f32.tf32.tf32.f32 "
        "{%0,%1,%2,%3},{%4,%5,%6,%7},{%8,%9},{%0,%1,%2,%3};"
        : "+f"(d[0]), "+f"(d[1]), "+f"(d[2]), "+f"(d[3])
        : "r"(a[0]), "r"(a[1]), "r"(a[2]), "r"(a[3]), "r"(b[0]), "r"(b[1]));
}

// ---------------- positional encoding ----------------
__global__ void pe_kernel(float* __restrict__ pe) {
    int i = blockIdx.x * 256 + threadIdx.x;
    if (i >= kLIN * kD) return;
    int pos = i / kD, d = i % kD;
    double rate = exp(-(double)(2 * (d / 2)) / (double)kD * log(10000.0));
    double ang  = (double)pos * rate;
    pe[i] = (float)((d & 1) ? cos(ang) : sin(ang));
}

// ---------------- embeddings ----------------
__global__ void embed_enc_kernel(const int* __restrict__ idx, const float* __restrict__ emb,
                                 const float* __restrict__ pe, float* __restrict__ x) {
    int t = blockIdx.x * 256 + threadIdx.x;
    if (t >= kB * kLIN * kD) return;
    int d = t & (kD - 1);
    int bs = t >> 9;
    int s  = bs % kLIN;
    float scale = sqrtf((float)kD);
    x[t] = emb[(size_t)idx[bs] * kD + d] * scale + pe[s * kD + d];
}
__global__ void embed_dec_kernel(const int* __restrict__ idx, const float* __restrict__ emb,
                                 const float* __restrict__ pe, float* __restrict__ x,
                                 float* __restrict__ eraw) {
    int t = blockIdx.x * 256 + threadIdx.x;
    if (t >= kB * kT * kD) return;
    int d = t & (kD - 1);
    int bs = t >> 9;
    int s  = bs % kT;
    float e = emb[(size_t)idx[bs] * kD + d];
    eraw[t] = e;
    float scale = sqrtf((float)kD);
    x[t] = e * scale + pe[s * kD + d];
}

// ---------------- tensor-core GEMM (3xTF32): C[M,N] = A[M,K] @ W[K,N] + bias ----
// Block tile 64(M) x 128(N), BK=16, 256 threads = 8 warps (2 M x 4 N),
// warp tile 32x32 via mma.m16n8k8 (2 m-tiles x 4 n-tiles).
// Precision: a = ah + al (tf32 split); acc += ah*bh + ah*bl + al*bh  (~fp32).
// Requires M%64==0, N%128==0, K%16==0 (true for all call sites).
__global__ void __launch_bounds__(256)
gemm_tc_kernel(const float* __restrict__ A, const float* __restrict__ W,
               const float* __restrict__ bias, float* __restrict__ C,
               int M, int N, int K, int ldc, int relu, const float* __restrict__ rs) {
    // pads chosen so row stride % 32 == 8 -> conflict-free frag reads & stores
    __shared__ uint32_t Ah[16][72],  Al[16][72];
    __shared__ uint32_t Bh[16][136], Bl[16][136];

    const int t    = threadIdx.x;
    const int lane = t & 31, wid = t >> 5;
    const int wm = wid & 1, wn = wid >> 1;        // 2 x 4 warp grid
    const int g = lane >> 2, c = lane & 3;        // mma fragment coords
    const int bm = blockIdx.y << 6, bn = blockIdx.x << 7;

    // global load mappings
    const int a_row = t & 63, a_kq = t >> 6;      // A: 64 rows x 4 float4 (k)
    const int b_k   = t >> 4, b_nq = t & 15;      // B: 16 k-rows x 16 float4 (n), x2

    float acc[2][4][4] = {};

    for (int k0 = 0; k0 < K; k0 += 16) {
        // ---- global -> regs ----
        float4 av  = *(const float4*)&A[(size_t)(bm + a_row) * K + k0 + (a_kq << 2)];
        float4 wv0 = *(const float4*)&W[(size_t)(k0 + b_k) * N + bn + (b_nq << 2)];
        float4 wv1 = *(const float4*)&W[(size_t)(k0 + b_k) * N + bn + (b_nq << 2) + 64];
        __syncthreads();   // previous tile consumed
        // ---- convert to tf32 hi/lo, store smem (k-major) ----
        {
            float a4[4] = {av.x, av.y, av.z, av.w};
            #pragma unroll
            for (int j = 0; j < 4; ++j) {
                uint32_t hi = f2tf32(a4[j]);
                Ah[(a_kq << 2) + j][a_row] = hi;
                Al[(a_kq << 2) + j][a_row] = f2tf32(a4[j] - __uint_as_float(hi));
            }
            float w4[8] = {wv0.x, wv0.y, wv0.z, wv0.w, wv1.x, wv1.y, wv1.z, wv1.w};
            #pragma unroll
            for (int j = 0; j < 4; ++j) {
                uint32_t hi0 = f2tf32(w4[j]);
                Bh[b_k][(b_nq << 2) + j] = hi0;
                Bl[b_k][(b_nq << 2) + j] = f2tf32(w4[j] - __uint_as_float(hi0));
                uint32_t hi1 = f2tf32(w4[4 + j]);
                Bh[b_k][64 + (b_nq << 2) + j] = hi1;
                Bl[b_k][64 + (b_nq << 2) + j] = f2tf32(w4[4 + j] - __uint_as_float(hi1));
            }
        }
        __syncthreads();
        // ---- compute: two k8 steps ----
        #pragma unroll
        for (int s = 0; s < 2; ++s) {
            const int kb = s << 3;
            uint32_t ah[2][4], al[2][4], bh[4][2], bl[4][2];
            #pragma unroll
            for (int mi = 0; mi < 2; ++mi) {
                int m = (wm << 5) + (mi << 4) + g;
                ah[mi][0] = Ah[kb + c][m];     ah[mi][1] = Ah[kb + c][m + 8];
                ah[mi][2] = Ah[kb + c + 4][m]; ah[mi][3] = Ah[kb + c + 4][m + 8];
                al[mi][0] = Al[kb + c][m];     al[mi][1] = Al[kb + c][m + 8];
                al[mi][2] = Al[kb + c + 4][m]; al[mi][3] = Al[kb + c + 4][m + 8];
            }
            #pragma unroll
            for (int ni = 0; ni < 4; ++ni) {
                int n = (wn << 5) + (ni << 3) + g;
                bh[ni][0] = Bh[kb + c][n]; bh[ni][1] = Bh[kb + c + 4][n];
                bl[ni][0] = Bl[kb + c][n]; bl[ni][1] = Bl[kb + c + 4][n];
            }
            #pragma unroll
            for (int mi = 0; mi < 2; ++mi)
                #pragma unroll
                for (int ni = 0; ni < 4; ++ni) {
                    mma_tf32(acc[mi][ni], al[mi], bh[ni]);
                    mma_tf32(acc[mi][ni], ah[mi], bl[ni]);
                    mma_tf32(acc[mi][ni], ah[mi], bh[ni]);
                }
        }
    }

    // ---- epilogue: bias, optional relu, optional row-scale ----
    #pragma unroll
    for (int mi = 0; mi < 2; ++mi) {
        int r0 = bm + (wm << 5) + (mi << 4) + g;
        float s0 = rs ? rs[r0] : 1.0f;
        float s1 = rs ? rs[r0 + 8] : 1.0f;
        #pragma unroll
        for (int ni = 0; ni < 4; ++ni) {
            int c0 = bn + (wn << 5) + (ni << 3) + (c << 1);
            float bb0 = bias[c0], bb1 = bias[c0 + 1];
            float v0 = acc[mi][ni][0] + bb0, v1 = acc[mi][ni][1] + bb1;
            float v2 = acc[mi][ni][2] + bb0, v3 = acc[mi][ni][3] + bb1;
            if (relu) {
                v0 = fmaxf(v0, 0.0f); v1 = fmaxf(v1, 0.0f);
                v2 = fmaxf(v2, 0.0f); v3 = fmaxf(v3, 0.0f);
            }
            *(float2*)&C[(size_t)r0 * ldc + c0]       = make_float2(v0 * s0, v1 * s0);
            *(float2*)&C[(size_t)(r0 + 8) * ldc + c0] = make_float2(v2 * s1, v3 * s1);
        }
    }
}

// ---------------- attention scores: S[b,h,q,k] = q.k/8 + mask*(-1e9) ----------------
__global__ void __launch_bounds__(256)
scores_kernel(const float* __restrict__ Q, const float* __restrict__ Kt,
              float* __restrict__ S, int Sq, int Sk,
              const float* __restrict__ mask, int mode) {
    __shared__ float Qs[32][68];
    __shared__ float Ks[32][68];
    int tid = threadIdx.x;
    int bh = blockIdx.z, b = bh >> 3, h = bh & 7;
    int q0 = blockIdx.y * 32, k0 = blockIdx.x * 32;
    for (int i = tid; i < 32 * 16; i += 256) {
        int r = i >> 4, c4 = (i & 15) << 2;
        float4 qv = make_float4(0, 0, 0, 0), kv = make_float4(0, 0, 0, 0);
        int qr = q0 + r, kr = k0 + r;
        if (qr < Sq) qv = *(const float4*)&Q[((size_t)(b * Sq + qr)) * kD + h * kDep + c4];
        if (kr < Sk) kv = *(const float4*)&Kt[((size_t)(b * Sk + kr)) * kD + h * kDep + c4];
        *(float4*)&Qs[r][c4] = qv;
        *(float4*)&Ks[r][c4] = kv;
    }
    __syncthreads();
    int tx = tid & 15, ty = tid >> 4;
    float acc[2][2] = {};
    #pragma unroll
    for (int d4 = 0; d4 < kDep; d4 += 4) {
        float4 a0 = *(const float4*)&Qs[ty * 2 + 0][d4];
        float4 a1 = *(const float4*)&Qs[ty * 2 + 1][d4];
        float4 b0 = *(const float4*)&Ks[tx * 2 + 0][d4];
        float4 b1 = *(const float4*)&Ks[tx * 2 + 1][d4];
        acc[0][0] += a0.x*b0.x + a0.y*b0.y + a0.z*b0.z + a0.w*b0.w;
        acc[0][1] += a0.x*b1.x + a0.y*b1.y + a0.z*b1.z + a0.w*b1.w;
        acc[1][0] += a1.x*b0.x + a1.y*b0.y + a1.z*b0.z + a1.w*b0.w;
        acc[1][1] += a1.x*b1.x + a1.y*b1.y + a1.z*b1.z + a1.w*b1.w;
    }
    #pragma unroll
    for (int i = 0; i < 2; ++i) {
        int qg = q0 + ty * 2 + i;
        #pragma unroll
        for (int j = 0; j < 2; ++j) {
            int kg = k0 + tx * 2 + j;
            if (qg < Sq && kg < Sk) {
                float vv = acc[i][j] * 0.125f;
                float mk = (mode == 0) ? mask[(size_t)b * Sk + kg]
                                       : mask[((size_t)b * Sq + qg) * Sk + kg];
                vv += mk * (-1e9f);
                S[((size_t)bh * Sq + qg) * Sk + kg] = vv;
            }
        }
    }
}

// ---------------- row softmax (in place) ----------------
__global__ void softmax_kernel(float* __restrict__ S, int len) {
    float* p = S + (size_t)blockIdx.x * len;
    int tid = threadIdx.x;
    __shared__ float sh[4];
    float m = -1e30f;
    for (int i = tid; i < len; i += 128) m = fmaxf(m, p[i]);
    m = warp_max(m);
    if ((tid & 31) == 0) sh[tid >> 5] = m;
    __syncthreads();
    m = fmaxf(fmaxf(sh[0], sh[1]), fmaxf(sh[2], sh[3]));
    float s = 0.0f;
    for (int i = tid; i < len; i += 128) { float e = __expf(p[i] - m); p[i] = e; s += e; }
    s = warp_sum(s);
    __syncthreads();
    if ((tid & 31) == 0) sh[tid >> 5] = s;
    __syncthreads();
    float inv = 1.0f / (sh[0] + sh[1] + sh[2] + sh[3]);
    for (int i = tid; i < len; i += 128) p[i] *= inv;
}

// ---------------- O[b,q,h*64+d] = sum_k P[b,h,q,k] * V[b,k,h*64+d] ----------------
__global__ void __launch_bounds__(256)
attn_out_kernel(const float* __restrict__ P, const float* __restrict__ V,
                float* __restrict__ O, int Sq, int Sk) {
    __shared__ float Ps[32][33];
    __shared__ float Vs[32][64];
    int tid = threadIdx.x;
    int bh = blockIdx.y, b = bh >> 3, h = bh & 7;
    int q0 = blockIdx.x * 32;
    const float* p = P + (size_t)bh * Sq * Sk;
    int dcol = tid & 63, qb = tid >> 6;
    float acc[8] = {};
    for (int k0 = 0; k0 < Sk; k0 += 32) {
        {
            int r = tid >> 3, cc = (tid & 7) << 2;
            int qg = q0 + r, kg = k0 + cc;
            float4 v4 = make_float4(0, 0, 0, 0);
            if (qg < Sq && kg < Sk)
                v4 = *(const float4*)&p[(size_t)qg * Sk + kg];
            Ps[r][cc] = v4.x; Ps[r][cc + 1] = v4.y; Ps[r][cc + 2] = v4.z; Ps[r][cc + 3] = v4.w;
        }
        for (int i = tid; i < 32 * 16; i += 256) {
            int r = i >> 4, c4 = (i & 15) << 2;
            int kg = k0 + r;
            float4 v4 = make_float4(0, 0, 0, 0);
            if (kg < Sk) v4 = *(const float4*)&V[((size_t)(b * Sk + kg)) * kD + h * kDep + c4];
            *(float4*)&Vs[r][c4] = v4;
        }
        __syncthreads();
        #pragma unroll
        for (int kk = 0; kk < 32; ++kk) {
            float vv = Vs[kk][dcol];
            #pragma unroll
            for (int j = 0; j < 8; ++j)
                acc[j] = fmaf(Ps[qb + (j << 2)][kk], vv, acc[j]);
        }
        __syncthreads();
    }
    #pragma unroll
    for (int j = 0; j < 8; ++j) {
        int qg = q0 + qb + (j << 2);
        if (qg < Sq) O[((size_t)(b * Sq + qg)) * kD + h * kDep + dcol] = acc[j];
    }
}

// ---------------- y = LN(x + a) * g + b ----------------
__global__ void add_ln_kernel(const float* __restrict__ x, const float* __restrict__ a,
                              float* __restrict__ y, const float* __restrict__ g,
                              const float* __restrict__ bb) {
    int row = blockIdx.x, tid = threadIdx.x;
    size_t base = (size_t)row * kD;
    float v[4], s = 0.0f, s2 = 0.0f;
    #pragma unroll
    for (int j = 0; j < 4; ++j) {
        int d = tid + j * 128;
        float t = x[base + d] + a[base + d];
        v[j] = t; s += t; s2 += t * t;
    }
    __shared__ float shs[4], shs2[4];
    s = warp_sum(s); s2 = warp_sum(s2);
    if ((tid & 31) == 0) { shs[tid >> 5] = s; shs2[tid >> 5] = s2; }
    __syncthreads();
    float S = shs[0] + shs[1] + shs[2] + shs[3];
    float S2 = shs2[0] + shs2[1] + shs2[2] + shs2[3];
    float mu = S * (1.0f / kD);
    float var = S2 * (1.0f / kD) - mu * mu;
    float rstd = rsqrtf(var + 1e-6f);
    #pragma unroll
    for (int j = 0; j < 4; ++j) {
        int d = tid + j * 128;
        y[base + d] = (v[j] - mu) * rstd * g[d] + bb[d];
    }
}

// ---------------- p_gen ----------------
__global__ void pgen_kernel(const float* __restrict__ ctx, const float* __restrict__ dec,
                            const float* __restrict__ emb, const float* __restrict__ w,
                            const float* __restrict__ bvec, float* __restrict__ pg) {
    int row = blockIdx.x, tid = threadIdx.x;
    float s = 0.0f;
    for (int d = tid; d < kD; d += 128) {
        size_t o = (size_t)row * kD + d;
        s += ctx[o] * w[d] + dec[o] * w[kD + d] + emb[o] * w[2 * kD + d];
    }
    __shared__ float sh[4];
    s = warp_sum(s);
    if ((tid & 31) == 0) sh[tid >> 5] = s;
    __syncthreads();
    if (tid == 0) {
        float t = sh[0] + sh[1] + sh[2] + sh[3] + bvec[0] + bvec[1] + bvec[2];
        pg[row] = 1.0f / (1.0f + expf(-t));
    }
}

// ---------------- attn_mean[b,t,l] = sum_h block2 / H ----------------
__global__ void attn_mean_kernel(const float* __restrict__ P, float* __restrict__ am) {
    int i = blockIdx.x * 256 + threadIdx.x;
    if (i >= kB * kT * kLIN) return;
    int l = i % kLIN;
    int bt = i / kLIN;
    int b = bt / kT, t = bt % kT;
    float s = 0.0f;
    #pragma unroll
    for (int h = 0; h < kH; ++h)
        s += P[(((size_t)(b * kH + h) * kT) + t) * kLIN + l];
    am[i] = s * (1.0f / kH);
}

// ---------------- zero extension columns [V, V+100) ----------------
__global__ void zero_ext_kernel(float* __restrict__ out) {
    int i = blockIdx.x * 256 + threadIdx.x;
    if (i >= kB * kT * kOOV) return;
    int row = i / kOOV, c = i % kOOV;
    out[(size_t)row * kVE + kV + c] = 0.0f;
}

// ---------------- copy scatter: out[b,t,ext[b,l]] += (1-pg)*am ----------------
__global__ void scatter_kernel(float* __restrict__ out, const float* __restrict__ am,
                               const float* __restrict__ pg, const int* __restrict__ ext) {
    int i = blockIdx.x * 256 + threadIdx.x;
    if (i >= kB * kT * kLIN) return;
    int l = i % kLIN;
    int bt = i / kLIN;
    int b = bt / kT;
    float v = (1.0f - pg[bt]) * am[i];
    int vi = ext[b * kLIN + l];
    atomicAdd(&out[(size_t)bt * kVE + vi], v);
}

// ---------------- host orchestration ----------------
extern "C" void kernel_launch(void* const* d_in, const int* in_sizes, int n_in,
                              void* d_out, int out_size) {
    int off = (n_in > 6 && in_sizes[6] == 1) ? 1 : 0;
    const int*   inp      = (const int*)d_in[0];
    const int*   tar      = (const int*)d_in[1];
    const int*   ext      = (const int*)d_in[2];
    const float* enc_mask = (const float*)d_in[3];
    const float* la_mask  = (const float*)d_in[4];
    const float* dec_mask = (const float*)d_in[5];
    const float* emb_enc  = (const float*)d_in[6 + off];
    const float* emb_dec  = (const float*)d_in[7 + off];
    const float* eaw = (const float*)d_in[8 + off];
    const float* eab = (const float*)d_in[9 + off];
    const float* ew1 = (const float*)d_in[10 + off];
    const float* eb1 = (const float*)d_in[11 + off];
    const float* ew2 = (const float*)d_in[12 + off];
    const float* eb2 = (const float*)d_in[13 + off];
    const float* elg = (const float*)d_in[14 + off];
    const float* elb = (const float*)d_in[15 + off];
    const float* daw = (const float*)d_in[16 + off];
    const float* dab = (const float*)d_in[17 + off];
    const float* dw1 = (const float*)d_in[18 + off];
    const float* db1 = (const float*)d_in[19 + off];
    const float* dw2 = (const float*)d_in[20 + off];
    const float* db2 = (const float*)d_in[21 + off];
    const float* dlg = (const float*)d_in[22 + off];
    const float* dlb = (const float*)d_in[23 + off];
    const float* ptrw = (const float*)d_in[24 + off];
    const float* ptrb = (const float*)d_in[25 + off];
    const float* fw  = (const float*)d_in[26 + off];
    const float* fb  = (const float*)d_in[27 + off];
    float* out = (float*)d_out;

    float *pe_, *xe_, *q_, *k_, *v_, *t_, *sc_, *cs_, *ffn_, *xd_, *emb_, *o1_, *o2_, *do_, *pg_, *am_;
    cudaGetSymbolAddress((void**)&pe_,  g_pe);
    cudaGetSymbolAddress((void**)&xe_,  g_xe);
    cudaGetSymbolAddress((void**)&q_,   g_q);
    cudaGetSymbolAddress((void**)&k_,   g_k);
    cudaGetSymbolAddress((void**)&v_,   g_v);
    cudaGetSymbolAddress((void**)&t_,   g_t);
    cudaGetSymbolAddress((void**)&sc_,  g_sc);
    cudaGetSymbolAddress((void**)&cs_,  g_cs);
    cudaGetSymbolAddress((void**)&ffn_, g_ffn);
    cudaGetSymbolAddress((void**)&xd_,  g_xd);
    cudaGetSymbolAddress((void**)&emb_, g_emb);
    cudaGetSymbolAddress((void**)&o1_,  g_o1);
    cudaGetSymbolAddress((void**)&o2_,  g_o2);
    cudaGetSymbolAddress((void**)&do_,  g_do);
    cudaGetSymbolAddress((void**)&pg_,  g_pg);
    cudaGetSymbolAddress((void**)&am_,  g_am);

    auto gemm = [&](const float* A, const float* W, const float* bias, float* C,
                    int M, int N, int K, int ldc, int relu, const float* rs) {
        dim3 grid(N / 128, M / 64);
        gemm_tc_kernel<<<grid, 256>>>(A, W, bias, C, M, N, K, ldc, relu, rs);
    };

    const int ME = kB * kLIN;  // 6400
    const int MD = kB * kT;    // 1600
    const size_t DD2 = (size_t)kD * kD;

    pe_kernel<<<(kLIN * kD + 255) / 256, 256>>>(pe_);
    embed_enc_kernel<<<(kB * kLIN * kD + 255) / 256, 256>>>(inp, emb_enc, pe_, xe_);

    // ================= encoder =================
    for (int i = 0; i < 2; ++i) {
        const float* w = eaw + (size_t)i * 4 * DD2;
        const float* b = eab + (size_t)i * 4 * kD;
        gemm(xe_, w + 0 * DD2, b + 0 * kD, q_, ME, kD, kD, kD, 0, nullptr);
        gemm(xe_, w + 1 * DD2, b + 1 * kD, k_, ME, kD, kD, kD, 0, nullptr);
        gemm(xe_, w + 2 * DD2, b + 2 * kD, v_, ME, kD, kD, kD, 0, nullptr);
        dim3 sg((kLIN + 31) / 32, (kLIN + 31) / 32, kB * kH);
        scores_kernel<<<sg, 256>>>(q_, k_, sc_, kLIN, kLIN, enc_mask, 0);
        softmax_kernel<<<kB * kH * kLIN, 128>>>(sc_, kLIN);
        dim3 og((kLIN + 31) / 32, kB * kH);
        attn_out_kernel<<<og, 256>>>(sc_, v_, t_, kLIN, kLIN);
        gemm(t_, w + 3 * DD2, b + 3 * kD, q_, ME, kD, kD, kD, 0, nullptr);
        add_ln_kernel<<<ME, 128>>>(xe_, q_, xe_, elg + (i * 2 + 0) * kD, elb + (i * 2 + 0) * kD);
        gemm(xe_, ew1 + (size_t)i * kD * kDFF, eb1 + (size_t)i * kDFF, ffn_, ME, kDFF, kD, kDFF, 1, nullptr);
        gemm(ffn_, ew2 + (size_t)i * kDFF * kD, eb2 + (size_t)i * kD, q_, ME, kD, kDFF, kD, 0, nullptr);
        add_ln_kernel<<<ME, 128>>>(xe_, q_, xe_, elg + (i * 2 + 1) * kD, elb + (i * 2 + 1) * kD);
    }

    // ================= decoder (only layer 1 is live; xd never updated in ref) =====
    embed_dec_kernel<<<(kB * kT * kD + 255) / 256, 256>>>(tar, emb_dec, pe_, xd_, emb_);
    {
        const int i = 1;
        const float* w0 = daw + (size_t)(i * 2 + 0) * 4 * DD2;
        const float* b0 = dab + (size_t)(i * 2 + 0) * 4 * kD;
        const float* w1 = daw + (size_t)(i * 2 + 1) * 4 * DD2;
        const float* b1 = dab + (size_t)(i * 2 + 1) * 4 * kD;
        gemm(xd_, w0 + 0 * DD2, b0 + 0 * kD, q_, MD, kD, kD, kD, 0, nullptr);
        gemm(xd_, w0 + 1 * DD2, b0 + 1 * kD, k_, MD, kD, kD, kD, 0, nullptr);
        gemm(xd_, w0 + 2 * DD2, b0 + 2 * kD, v_, MD, kD, kD, kD, 0, nullptr);
        scores_kernel<<<dim3((kT + 31) / 32, (kT + 31) / 32, kB * kH), 256>>>(q_, k_, sc_, kT, kT, la_mask, 1);
        softmax_kernel<<<kB * kH * kT, 128>>>(sc_, kT);
        attn_out_kernel<<<dim3((kT + 31) / 32, kB * kH), 256>>>(sc_, v_, t_, kT, kT);
        gemm(t_, w0 + 3 * DD2, b0 + 3 * kD, q_, MD, kD, kD, kD, 0, nullptr);
        add_ln_kernel<<<MD, 128>>>(xd_, q_, o1_, dlg + (i * 3 + 0) * kD, dlb + (i * 3 + 0) * kD);
        gemm(o1_, w1 + 0 * DD2, b1 + 0 * kD, q_, MD, kD, kD, kD, 0, nullptr);
        gemm(xe_, w1 + 1 * DD2, b1 + 1 * kD, k_, ME, kD, kD, kD, 0, nullptr);
        gemm(xe_, w1 + 2 * DD2, b1 + 2 * kD, v_, ME, kD, kD, kD, 0, nullptr);
        scores_kernel<<<dim3((kLIN + 31) / 32, (kT + 31) / 32, kB * kH), 256>>>(q_, k_, cs_, kT, kLIN, dec_mask, 0);
        softmax_kernel<<<kB * kH * kT, 128>>>(cs_, kLIN);
        attn_out_kernel<<<dim3((kT + 31) / 32, kB * kH), 256>>>(cs_, v_, t_, kT, kLIN);
        gemm(t_, w1 + 3 * DD2, b1 + 3 * kD, q_, MD, kD, kD, kD, 0, nullptr);
        add_ln_kernel<<<MD, 128>>>(o1_, q_, o2_, dlg + (i * 3 + 1) * kD, dlb + (i * 3 + 1) * kD);
        gemm(o2_, dw1 + (size_t)i * kD * kDFF, db1 + (size_t)i * kDFF, ffn_, MD, kDFF, kD, kDFF, 1, nullptr);
        gemm(ffn_, dw2 + (size_t)i * kDFF * kD, db2 + (size_t)i * kD, q_, MD, kD, kDFF, kD, 0, nullptr);
        add_ln_kernel<<<MD, 128>>>(o2_, q_, do_, dlg + (i * 3 + 2) * kD, dlb + (i * 3 + 2) * kD);
    }

    // ================= pointer-generator head =================
    attn_out_kernel<<<dim3((kT + 31) / 32, kB * kH), 256>>>(cs_, xe_, t_, kT, kLIN);
    pgen_kernel<<<MD, 128>>>(t_, do_, emb_, ptrw, ptrb, pg_);
    gemm(do_, fw, fb, out, MD, kV, kD, kVE, 0, pg_);
    zero_ext_kernel<<<(kB * kT * kOOV + 255) / 256, 256>>>(out);
    attn_mean_kernel<<<(kB * kT * kLIN + 255) / 256, 256>>>(cs_, am_);
    if (out_size >= kB * kT * kVE + kB * kT * kLIN)
        cudaMemcpyAsync(out + (size_t)kB * kT * kVE, am_,
                        sizeof(float) * kB * kT * kLIN, cudaMemcpyDeviceToDevice, 0);
    scatter_kernel<<<(kB * kT * kLIN + 255) / 256, 256>>>(out, am_, pg_, ext);
}